// round 10
// baseline (speedup 1.0000x reference)
#include <cuda_runtime.h>

#define FH 50
#define FW 50
#define CH 256
#define BATCH 4
#define NROI 1024
#define HOUT 7
#define WOUT 7
#define NBIN (HOUT*WOUT)
#define NBH 25                    // max bins per half-roi CTA
#define RATIO (1.0f/32.0f)
#define NGRP 4
#define TPB (128*NGRP)
#define NWARP (TPB/32)
#define HW (FH*FW)

// smem: tile[CH*NBH] f32 + 4 offset int4[NBH] + 2 weight float4[NBH] + flag int[NBH]
#define SMEM_BYTES (CH*NBH*4 + 4*NBH*16 + 2*NBH*16 + NBH*4)

// Features transposed to BHWC so channel reads are contiguous.
__device__ float g_feats[BATCH * HW * CH];

// ---------------------------------------------------------------------------
// Kernel 1: BCHW -> BHWC, classic 32x32 smem-tiled transpose per batch.
// ---------------------------------------------------------------------------
__global__ void transpose_feats_kernel(const float* __restrict__ in) {
    __shared__ float t[32][33];
    int b  = blockIdx.z;
    int c0 = blockIdx.x * 32;
    int p0 = blockIdx.y * 32;
    const float* src = in + (size_t)b * CH * HW;
    float* dst = g_feats + (size_t)b * HW * CH;

    int p = p0 + threadIdx.x;
#pragma unroll
    for (int i = 0; i < 32; i += 8) {
        int c = c0 + threadIdx.y + i;
        if (p < HW)
            t[threadIdx.y + i][threadIdx.x] = src[(size_t)c * HW + p];
    }
    __syncthreads();
    int c = c0 + threadIdx.x;
#pragma unroll
    for (int i = 0; i < 32; i += 8) {
        int pp = p0 + threadIdx.y + i;
        if (pp < HW)
            dst[(size_t)pp * CH + c] = t[threadIdx.x][threadIdx.y + i];
    }
}

// bilinear + max for one sample (float2 = 2 channels)
#define SAMPLE(m0, m1, q00, q01, q10, q11, xh, xl, yb, yt)          \
    do {                                                            \
        float top0 = (xh) * (q01).x + (xl) * (q00).x;               \
        float bot0 = (xh) * (q11).x + (xl) * (q10).x;               \
        float top1 = (xh) * (q01).y + (xl) * (q00).y;               \
        float bot1 = (xh) * (q11).y + (xl) * (q10).y;               \
        m0 = fmaxf(m0, (yb) * bot0 + (yt) * top0);                  \
        m1 = fmaxf(m1, (yb) * bot1 + (yt) * top1);                  \
    } while (0)

// ---------------------------------------------------------------------------
// Kernel 2: RoIAlign, HALF-roi per CTA (grid 2*NROI, 3 CTAs/SM; R9 verified
// occ=68.6% with L2 sane). Phase C rewritten warp-structured: lane = bin,
// warp strides channels — zero div/mod in the epilogue (R9's alu=36% bug).
// ---------------------------------------------------------------------------
__global__ __launch_bounds__(TPB, 3)
void roialign_kernel(const float* __restrict__ rois,
                     float* __restrict__ out) {
    extern __shared__ float smem[];
    float*  tile   = smem;                              // [CH][NBH]
    int4*   g_offA = (int4*)(smem + CH * NBH);          // [NBH] a00,a01,a10,a11
    int4*   g_offB = g_offA + NBH;
    int4*   g_offC = g_offB + NBH;
    int4*   g_offD = g_offC + NBH;
    float4* g_wy   = (float4*)(g_offD + NBH);           // [NBH] wyb0,wyt0,wyb1,wyt1 (0 if invalid)
    float4* g_wx   = g_wy + NBH;                        // [NBH] wxh0,wxl0,wxh1,wxl1
    int*    g_flag = (int*)(g_wx + NBH);                // [NBH] bit0 sameX, bit1 sameY

    int r     = blockIdx.x >> 1;
    int half  = blockIdx.x & 1;
    int kbase = half * NBH;            // 0 or 25
    int nbins = NBH - half;            // 25 or 24
    int tid   = threadIdx.x;

    int b = (int)__ldg(&rois[r * 5 + 0]);
    const float2* fbase = (const float2*)g_feats + (size_t)b * HW * (CH / 2);

    // ---- Phase A ----
    if (tid < nbins) {
        float bx1 = fminf(fmaxf(__ldg(&rois[r * 5 + 1]) * RATIO, 0.f), (float)FW);
        float by1 = fminf(fmaxf(__ldg(&rois[r * 5 + 2]) * RATIO, 0.f), (float)FH);
        float bx2 = fminf(fmaxf(__ldg(&rois[r * 5 + 3]) * RATIO, 0.f), (float)FW);
        float by2 = fminf(fmaxf(__ldg(&rois[r * 5 + 4]) * RATIO, 0.f), (float)FH);
        bool roi_valid = (bx2 - bx1 > 0.f) && (by2 - by1 > 0.f);
        float bin_w = (bx2 - bx1) * (1.0f / WOUT);
        float bin_h = (by2 - by1) * (1.0f / HOUT);

        int kg = kbase + tid;          // global bin index
        int i = kg / WOUT;
        int j = kg - i * WOUT;

        float y1u = by1 + (float)i * bin_h;
        float y1b = fminf(fmaxf(y1u, 0.f), (float)FH);
        float y2b = fminf(fmaxf(y1u + bin_h, 0.f), (float)FH);
        float x1u = bx1 + (float)j * bin_w;
        float x1b = fminf(fmaxf(x1u, 0.f), (float)FW);
        float x2b = fminf(fmaxf(x1u + bin_w, 0.f), (float)FW);
        bool valid = roi_valid && (x2b > x1b) && (y2b > y1b);
        float vscale = valid ? 1.f : 0.f;

        int   rowi[4], coli[4];
        float wyv[4], wxv[4];
#pragma unroll
        for (int t = 0; t < 2; t++) {
            float py = y1b + ((float)t + 0.5f) * (bin_h * 0.5f);
            float yl = fminf(fmaxf(floorf(py), 0.f), (float)(FH - 1));
            int ylI = (int)yl;
            int yhI = min(ylI + 1, FH - 1);
            rowi[2 * t + 0] = ylI * FW * (CH / 2);
            rowi[2 * t + 1] = yhI * FW * (CH / 2);
            wyv[2 * t + 0] = (py - yl) * vscale;          // wyb (zeroed if invalid)
            wyv[2 * t + 1] = ((float)yhI - py) * vscale;  // wyt (NOT 1-wyb)

            float px = x1b + ((float)t + 0.5f) * (bin_w * 0.5f);
            float xl = fminf(fmaxf(floorf(px), 0.f), (float)(FW - 1));
            int xlI = (int)xl;
            int xhI = min(xlI + 1, FW - 1);
            coli[2 * t + 0] = xlI * (CH / 2);
            coli[2 * t + 1] = xhI * (CH / 2);
            wxv[2 * t + 0] = px - xl;          // wxh
            wxv[2 * t + 1] = (float)xhI - px;  // wxl
        }
        g_offA[tid] = make_int4(rowi[0] + coli[0], rowi[0] + coli[1],
                                rowi[1] + coli[0], rowi[1] + coli[1]);
        g_offB[tid] = make_int4(rowi[0] + coli[2], rowi[0] + coli[3],
                                rowi[1] + coli[2], rowi[1] + coli[3]);
        g_offC[tid] = make_int4(rowi[2] + coli[0], rowi[2] + coli[1],
                                rowi[3] + coli[0], rowi[3] + coli[1]);
        g_offD[tid] = make_int4(rowi[2] + coli[2], rowi[2] + coli[3],
                                rowi[3] + coli[2], rowi[3] + coli[3]);
        g_wy[tid] = make_float4(wyv[0], wyv[1], wyv[2], wyv[3]);
        g_wx[tid] = make_float4(wxv[0], wxv[1], wxv[2], wxv[3]);
        int sameX = (coli[2] == coli[0]) && (coli[3] == coli[1]);
        int sameY = (rowi[2] == rowi[0]) && (rowi[3] == rowi[1]);
        g_flag[tid] = sameX | (sameY << 1);
    }
    __syncthreads();

    // ---- Phase B ----
    int c2  = tid & 127;       // channel pair 0..127
    int grp = tid >> 7;        // bin group 0..3
    const float2* fb2 = fbase + c2;

    for (int k = grp; k < nbins; k += NGRP) {
        int4   oA = g_offA[k];
        float4 wy = g_wy[k];
        float4 wx = g_wx[k];
        int    fl = g_flag[k];
        bool sameX = fl & 1;
        bool sameY = fl & 2;

        // Corner set A (always needed)
        float2 a00 = fb2[oA.x];
        float2 a01 = fb2[oA.y];
        float2 a10 = fb2[oA.z];
        float2 a11 = fb2[oA.w];

        float v0 = wx.x * a01.x + wx.y * a00.x;   // sample(0,0) top
        float w0 = wx.x * a11.x + wx.y * a10.x;   // bot
        float v1 = wx.x * a01.y + wx.y * a00.y;
        float w1 = wx.x * a11.y + wx.y * a10.y;
        float m0 = wy.x * w0 + wy.y * v0;
        float m1 = wy.x * w1 + wy.y * v1;

        // Corner set B: rows pair0 x cols pair1
        float2 b00, b01, b10, b11;
        if (sameX) { b00 = a00; b01 = a01; b10 = a10; b11 = a11; }
        else {
            int4 oB = g_offB[k];
            b00 = fb2[oB.x]; b01 = fb2[oB.y]; b10 = fb2[oB.z]; b11 = fb2[oB.w];
        }
        SAMPLE(m0, m1, b00, b01, b10, b11, wx.z, wx.w, wy.x, wy.y);

        // Corner sets C (rows pair1 x cols pair0) and D (rows pair1 x cols pair1)
        float2 c00, c01, c10, c11, d00, d01, d10, d11;
        if (sameY) {
            c00 = a00; c01 = a01; c10 = a10; c11 = a11;
            d00 = b00; d01 = b01; d10 = b10; d11 = b11;
        } else {
            int4 oC = g_offC[k];
            c00 = fb2[oC.x]; c01 = fb2[oC.y]; c10 = fb2[oC.z]; c11 = fb2[oC.w];
            if (sameX) { d00 = c00; d01 = c01; d10 = c10; d11 = c11; }
            else {
                int4 oD = g_offD[k];
                d00 = fb2[oD.x]; d01 = fb2[oD.y]; d10 = fb2[oD.z]; d11 = fb2[oD.w];
            }
        }
        SAMPLE(m0, m1, c00, c01, c10, c11, wx.x, wx.y, wy.z, wy.w);
        SAMPLE(m0, m1, d00, d01, d10, d11, wx.z, wx.w, wy.z, wy.w);

        tile[(2 * c2 + 0) * NBH + k] = m0;
        tile[(2 * c2 + 1) * NBH + k] = m1;
    }
    __syncthreads();

    // ---- Phase C: warp-structured flush, no div/mod. lane = bin index,
    // each warp walks channels c = warp, warp+16, ... (16 unrolled iters). ----
    {
        int warp = tid >> 5;
        int lane = tid & 31;
        if (lane < nbins) {
            const float* srcp = tile + warp * NBH + lane;
            float* dstp = out + (size_t)r * CH * NBIN + kbase + warp * NBIN + lane;
#pragma unroll
            for (int it = 0; it < CH / NWARP; it++) {
                *dstp = *srcp;
                srcp += NWARP * NBH;
                dstp += NWARP * NBIN;
            }
        }
    }
}

extern "C" void kernel_launch(void* const* d_in, const int* in_sizes, int n_in,
                              void* d_out, int out_size) {
    const float* feats = (const float*)d_in[0];   // (4,256,50,50) f32
    const float* rois  = (const float*)d_in[1];   // (1024,5) f32
    float* out = (float*)d_out;                   // (1024,256,7,7) f32

    cudaFuncSetAttribute(roialign_kernel,
                         cudaFuncAttributeMaxDynamicSharedMemorySize, SMEM_BYTES);

    dim3 tgrid(CH / 32, (HW + 31) / 32, BATCH);
    dim3 tblk(32, 8);
    transpose_feats_kernel<<<tgrid, tblk>>>(feats);
    roialign_kernel<<<NROI * 2, TPB, SMEM_BYTES>>>(rois, out);
}

// round 11
// speedup vs baseline: 1.1041x; 1.1041x over previous
#include <cuda_runtime.h>

#define FH 50
#define FW 50
#define CH 256
#define BATCH 4
#define NROI 1024
#define HOUT 7
#define WOUT 7
#define NBIN (HOUT*WOUT)
#define RATIO (1.0f/32.0f)
#define NGRP 4
#define TPB (128*NGRP)
#define HW (FH*FW)

// smem: tile[CH*NBIN] f32 + oA int4[NBIN] + wy/wx float4[NBIN] + fd int4[NBIN]
#define SMEM_BYTES (CH*NBIN*4 + NBIN*16*4)

// Features transposed to BHWC so channel reads are contiguous.
__device__ float g_feats[BATCH * HW * CH];

// ---------------------------------------------------------------------------
// Kernel 1: BCHW -> BHWC, classic 32x32 smem-tiled transpose per batch.
// ---------------------------------------------------------------------------
__global__ void transpose_feats_kernel(const float* __restrict__ in) {
    __shared__ float t[32][33];
    int b  = blockIdx.z;
    int c0 = blockIdx.x * 32;
    int p0 = blockIdx.y * 32;
    const float* src = in + (size_t)b * CH * HW;
    float* dst = g_feats + (size_t)b * HW * CH;

    int p = p0 + threadIdx.x;
#pragma unroll
    for (int i = 0; i < 32; i += 8) {
        int c = c0 + threadIdx.y + i;
        if (p < HW)
            t[threadIdx.y + i][threadIdx.x] = src[(size_t)c * HW + p];
    }
    __syncthreads();
    int c = c0 + threadIdx.x;
#pragma unroll
    for (int i = 0; i < 32; i += 8) {
        int pp = p0 + threadIdx.y + i;
        if (pp < HW)
            dst[(size_t)pp * CH + c] = t[threadIdx.x][threadIdx.y + i];
    }
}

// bilinear + max for one sample (float2 = 2 channels)
#define SAMPLE(m0, m1, q00, q01, q10, q11, xh, xl, yb, yt)          \
    do {                                                            \
        float top0 = (xh) * (q01).x + (xl) * (q00).x;               \
        float bot0 = (xh) * (q11).x + (xl) * (q10).x;               \
        float top1 = (xh) * (q01).y + (xl) * (q00).y;               \
        float bot1 = (xh) * (q11).y + (xl) * (q10).y;               \
        m0 = fmaxf(m0, (yb) * bot0 + (yt) * top0);                  \
        m1 = fmaxf(m1, (yb) * bot1 + (yt) * top1);                  \
    } while (0)

__device__ __forceinline__ float2 sel2(bool p, float2 a, float2 b) {
    float2 r; r.x = p ? a.x : b.x; r.y = p ? a.y : b.y; return r;
}

// ---------------------------------------------------------------------------
// Kernel 2: RoIAlign. One block per FULL roi (R8 config: grid 1024, 512 thr,
// 2 CTAs/SM — the verified L1D sweet spot). Adjacent-cell algebra: when the
// 2x2 samples don't share a cell they sit in ADJACENT cells, so corner sets
// B/C/D need only 2/2/1 incremental loads (avg 5.25 loads/bin vs 6.7).
// ---------------------------------------------------------------------------
__global__ __launch_bounds__(TPB, 2)
void roialign_kernel(const float* __restrict__ rois,
                     float* __restrict__ out) {
    extern __shared__ float smem[];
    float*  tile   = smem;                              // [CH][NBIN]
    int4*   g_offA = (int4*)(smem + CH * NBIN);         // [NBIN] a00,a01,a10,a11 (float2 units)
    float4* g_wy   = (float4*)(g_offA + NBIN);          // [NBIN] wyb0,wyt0,wyb1,wyt1 (0 if invalid)
    float4* g_wx   = g_wy + NBIN;                       // [NBIN] wxh0,wxl0,wxh1,wxl1
    int4*   g_fd   = (int4*)(g_wx + NBIN);              // [NBIN] dcol,drow,sameX,sameY

    int r   = blockIdx.x;
    int tid = threadIdx.x;

    int b = (int)__ldg(&rois[r * 5 + 0]);
    const float2* fbase = (const float2*)g_feats + (size_t)b * HW * (CH / 2);

    // ---- Phase A ----
    if (tid < NBIN) {
        float bx1 = fminf(fmaxf(__ldg(&rois[r * 5 + 1]) * RATIO, 0.f), (float)FW);
        float by1 = fminf(fmaxf(__ldg(&rois[r * 5 + 2]) * RATIO, 0.f), (float)FH);
        float bx2 = fminf(fmaxf(__ldg(&rois[r * 5 + 3]) * RATIO, 0.f), (float)FW);
        float by2 = fminf(fmaxf(__ldg(&rois[r * 5 + 4]) * RATIO, 0.f), (float)FH);
        bool roi_valid = (bx2 - bx1 > 0.f) && (by2 - by1 > 0.f);
        float bin_w = (bx2 - bx1) * (1.0f / WOUT);
        float bin_h = (by2 - by1) * (1.0f / HOUT);

        int i = tid / WOUT;
        int j = tid - i * WOUT;

        float y1u = by1 + (float)i * bin_h;
        float y1b = fminf(fmaxf(y1u, 0.f), (float)FH);
        float y2b = fminf(fmaxf(y1u + bin_h, 0.f), (float)FH);
        float x1u = bx1 + (float)j * bin_w;
        float x1b = fminf(fmaxf(x1u, 0.f), (float)FW);
        float x2b = fminf(fmaxf(x1u + bin_w, 0.f), (float)FW);
        bool valid = roi_valid && (x2b > x1b) && (y2b > y1b);
        float vscale = valid ? 1.f : 0.f;

        int   rowi[4], coli[4];
        float wyv[4], wxv[4];
#pragma unroll
        for (int t = 0; t < 2; t++) {
            float py = y1b + ((float)t + 0.5f) * (bin_h * 0.5f);
            float yl = fminf(fmaxf(floorf(py), 0.f), (float)(FH - 1));
            int ylI = (int)yl;
            int yhI = min(ylI + 1, FH - 1);
            rowi[2 * t + 0] = ylI * FW * (CH / 2);
            rowi[2 * t + 1] = yhI * FW * (CH / 2);
            wyv[2 * t + 0] = (py - yl) * vscale;          // wyb (zeroed if invalid)
            wyv[2 * t + 1] = ((float)yhI - py) * vscale;  // wyt (NOT 1-wyb)

            float px = x1b + ((float)t + 0.5f) * (bin_w * 0.5f);
            float xl = fminf(fmaxf(floorf(px), 0.f), (float)(FW - 1));
            int xlI = (int)xl;
            int xhI = min(xlI + 1, FW - 1);
            coli[2 * t + 0] = xlI * (CH / 2);
            coli[2 * t + 1] = xhI * (CH / 2);
            wxv[2 * t + 0] = px - xl;          // wxh
            wxv[2 * t + 1] = (float)xhI - px;  // wxl
        }
        g_offA[tid] = make_int4(rowi[0] + coli[0], rowi[0] + coli[1],
                                rowi[1] + coli[0], rowi[1] + coli[1]);
        g_wy[tid] = make_float4(wyv[0], wyv[1], wyv[2], wyv[3]);
        g_wx[tid] = make_float4(wxv[0], wxv[1], wxv[2], wxv[3]);
        int sameX = (coli[2] == coli[0]) && (coli[3] == coli[1]);
        int sameY = (rowi[2] == rowi[0]) && (rowi[3] == rowi[1]);
        // deltas to the new column / new row (0 at clamp boundaries, in which
        // case the "new" load aliases an existing corner address — still correct)
        g_fd[tid] = make_int4(coli[3] - coli[1], rowi[3] - rowi[1], sameX, sameY);
    }
    __syncthreads();

    // ---- Phase B ----
    int c2  = tid & 127;       // channel pair 0..127
    int grp = tid >> 7;        // bin group 0..3
    const float2* fb2 = fbase + c2;

    for (int k = grp; k < NBIN; k += NGRP) {
        int4   oA = g_offA[k];
        float4 wy = g_wy[k];
        float4 wx = g_wx[k];
        int4   fd = g_fd[k];
        int dcol = fd.x, drow = fd.y;
        bool sameX = fd.z, sameY = fd.w;

        // Corner set A (always)
        float2 a00 = fb2[oA.x];
        float2 a01 = fb2[oA.y];
        float2 a10 = fb2[oA.z];
        float2 a11 = fb2[oA.w];

        float v0 = wx.x * a01.x + wx.y * a00.x;   // sample(0,0)
        float w0 = wx.x * a11.x + wx.y * a10.x;
        float v1 = wx.x * a01.y + wx.y * a00.y;
        float w1 = wx.x * a11.y + wx.y * a10.y;
        float m0 = wy.x * w0 + wy.y * v0;
        float m1 = wy.x * w1 + wy.y * v1;

        // Corner set B (rows pair0 x cols pair1): !sameX => xl1 == xh0, so
        // b00=a01, b10=a11 and only the xh1 column (2 loads) is new.
        float2 b00, b01, b10, b11;
        if (!sameX) {
            b00 = a01; b10 = a11;
            b01 = fb2[oA.y + dcol];
            b11 = fb2[oA.w + dcol];
        } else {
            b00 = a00; b01 = a01; b10 = a10; b11 = a11;
        }
        SAMPLE(m0, m1, b00, b01, b10, b11, wx.z, wx.w, wy.x, wy.y);

        // Corner set C (rows pair1 x cols pair0): !sameY => yl1 == yh0, so
        // c00=a10, c01=a11 and only the yh1 row (2 loads) is new.
        float2 c00, c01, c10, c11;
        if (!sameY) {
            c00 = a10; c01 = a11;
            c10 = fb2[oA.z + drow];
            c11 = fb2[oA.w + drow];
        } else {
            c00 = a00; c01 = a01; c10 = a10; c11 = a11;
        }
        SAMPLE(m0, m1, c00, c01, c10, c11, wx.x, wx.y, wy.z, wy.w);

        // Corner set D (rows pair1 x cols pair1): at most ONE new load
        // (the far diagonal); the rest are reuses of a/b/c corners.
        float2 d00 = sel2(sameX, c00, c01);
        float2 d01 = sameX ? c01 : (sameY ? b01 : b11);
        float2 d10 = sel2(sameX, c10, c11);
        float2 d11;
        if (sameX)      d11 = c11;
        else if (sameY) d11 = b11;
        else            d11 = fb2[oA.w + drow + dcol];
        SAMPLE(m0, m1, d00, d01, d10, d11, wx.z, wx.w, wy.z, wy.w);

        tile[(2 * c2 + 0) * NBIN + k] = m0;
        tile[(2 * c2 + 1) * NBIN + k] = m1;
    }
    __syncthreads();

    // ---- Phase C: tile[c*49 + k] is exactly (N,C,7,7) order for this roi ----
    float4* dst4       = (float4*)(out + (size_t)r * CH * NBIN);
    const float4* src4 = (const float4*)tile;
    for (int idx = tid; idx < CH * NBIN / 4; idx += blockDim.x)
        dst4[idx] = src4[idx];
}

extern "C" void kernel_launch(void* const* d_in, const int* in_sizes, int n_in,
                              void* d_out, int out_size) {
    const float* feats = (const float*)d_in[0];   // (4,256,50,50) f32
    const float* rois  = (const float*)d_in[1];   // (1024,5) f32
    float* out = (float*)d_out;                   // (1024,256,7,7) f32

    cudaFuncSetAttribute(roialign_kernel,
                         cudaFuncAttributeMaxDynamicSharedMemorySize, SMEM_BYTES);

    dim3 tgrid(CH / 32, (HW + 31) / 32, BATCH);
    dim3 tblk(32, 8);
    transpose_feats_kernel<<<tgrid, tblk>>>(feats);
    roialign_kernel<<<NROI, TPB, SMEM_BYTES>>>(rois, out);
}

// round 12
// speedup vs baseline: 1.2302x; 1.1142x over previous
#include <cuda_runtime.h>

#define FH 50
#define FW 50
#define CH 256
#define BATCH 4
#define NROI 1024
#define HOUT 7
#define WOUT 7
#define NBIN (HOUT*WOUT)
#define RATIO (1.0f/32.0f)
#define NGRP 4
#define TPB (128*NGRP)
#define HW (FH*FW)

// smem: tile[CH*NBIN] f32 + rows int4[NBIN] + cols int4[NBIN] + wy/wx float4[NBIN]
#define SMEM_BYTES (CH*NBIN*4 + NBIN*16*4)

// Features transposed to BHWC so channel reads are contiguous.
__device__ float g_feats[BATCH * HW * CH];

// ---------------------------------------------------------------------------
// Kernel 1: BCHW -> BHWC, classic 32x32 smem-tiled transpose per batch.
// ---------------------------------------------------------------------------
__global__ void transpose_feats_kernel(const float* __restrict__ in) {
    __shared__ float t[32][33];
    int b  = blockIdx.z;
    int c0 = blockIdx.x * 32;
    int p0 = blockIdx.y * 32;
    const float* src = in + (size_t)b * CH * HW;
    float* dst = g_feats + (size_t)b * HW * CH;

    int p = p0 + threadIdx.x;
#pragma unroll
    for (int i = 0; i < 32; i += 8) {
        int c = c0 + threadIdx.y + i;
        if (p < HW)
            t[threadIdx.y + i][threadIdx.x] = src[(size_t)c * HW + p];
    }
    __syncthreads();
    int c = c0 + threadIdx.x;
#pragma unroll
    for (int i = 0; i < 32; i += 8) {
        int pp = p0 + threadIdx.y + i;
        if (pp < HW)
            dst[(size_t)pp * CH + c] = t[threadIdx.x][threadIdx.y + i];
    }
}

// x-interp on a channel pair: xh*fh + xl*fl (reference expression form)
__device__ __forceinline__ float2 xin(float xh, float xl, float2 fh, float2 fl) {
    float2 r;
    r.x = xh * fh.x + xl * fl.x;
    r.y = xh * fh.y + xl * fl.y;
    return r;
}
// y-combine + max accumulate: m = max(m, yb*hb + yt*ht) per channel
#define YMAX(m0, m1, yb, yt, hb, ht)                 \
    do {                                             \
        m0 = fmaxf(m0, (yb) * (hb).x + (yt) * (ht).x); \
        m1 = fmaxf(m1, (yb) * (hb).y + (yt) * (ht).y); \
    } while (0)

// ---------------------------------------------------------------------------
// Kernel 2: RoIAlign. One block per FULL roi (grid 1024, 512 thr, 2 CTAs/SM —
// the verified L1D sweet spot). Factorized bilinear: x-interp values h[row][t]
// are computed once per distinct row and shared across the 2x2 samples, using
// the adjacency identities (!sameX => xl1==xh0, !sameY => yl1==yh0). Four
// warp-uniform specialized paths, zero data-muxing selects.
//   rows r0=yl0, r1=yh0, r2=yh1 ; cols c0=xl0, c1=xh0, c2=xh1 (float2 units)
// ---------------------------------------------------------------------------
__global__ __launch_bounds__(TPB, 2)
void roialign_kernel(const float* __restrict__ rois,
                     float* __restrict__ out) {
    extern __shared__ float smem[];
    float*  tile   = smem;                              // [CH][NBIN]
    int4*   g_rows = (int4*)(smem + CH * NBIN);         // [NBIN] r0,r1,r2,flags
    int4*   g_cols = g_rows + NBIN;                     // [NBIN] c0,c1,c2,0
    float4* g_wy   = (float4*)(g_cols + NBIN);          // [NBIN] wyb0,wyt0,wyb1,wyt1 (0 if invalid)
    float4* g_wx   = g_wy + NBIN;                       // [NBIN] wxh0,wxl0,wxh1,wxl1

    int r   = blockIdx.x;
    int tid = threadIdx.x;

    int b = (int)__ldg(&rois[r * 5 + 0]);
    const float2* fbase = (const float2*)g_feats + (size_t)b * HW * (CH / 2);

    // ---- Phase A ----
    if (tid < NBIN) {
        float bx1 = fminf(fmaxf(__ldg(&rois[r * 5 + 1]) * RATIO, 0.f), (float)FW);
        float by1 = fminf(fmaxf(__ldg(&rois[r * 5 + 2]) * RATIO, 0.f), (float)FH);
        float bx2 = fminf(fmaxf(__ldg(&rois[r * 5 + 3]) * RATIO, 0.f), (float)FW);
        float by2 = fminf(fmaxf(__ldg(&rois[r * 5 + 4]) * RATIO, 0.f), (float)FH);
        bool roi_valid = (bx2 - bx1 > 0.f) && (by2 - by1 > 0.f);
        float bin_w = (bx2 - bx1) * (1.0f / WOUT);
        float bin_h = (by2 - by1) * (1.0f / HOUT);

        int i = tid / WOUT;
        int j = tid - i * WOUT;

        float y1u = by1 + (float)i * bin_h;
        float y1b = fminf(fmaxf(y1u, 0.f), (float)FH);
        float y2b = fminf(fmaxf(y1u + bin_h, 0.f), (float)FH);
        float x1u = bx1 + (float)j * bin_w;
        float x1b = fminf(fmaxf(x1u, 0.f), (float)FW);
        float x2b = fminf(fmaxf(x1u + bin_w, 0.f), (float)FW);
        bool valid = roi_valid && (x2b > x1b) && (y2b > y1b);
        float vscale = valid ? 1.f : 0.f;

        int   rowi[4], coli[4];
        float wyv[4], wxv[4];
#pragma unroll
        for (int t = 0; t < 2; t++) {
            float py = y1b + ((float)t + 0.5f) * (bin_h * 0.5f);
            float yl = fminf(fmaxf(floorf(py), 0.f), (float)(FH - 1));
            int ylI = (int)yl;
            int yhI = min(ylI + 1, FH - 1);
            rowi[2 * t + 0] = ylI * FW * (CH / 2);
            rowi[2 * t + 1] = yhI * FW * (CH / 2);
            wyv[2 * t + 0] = (py - yl) * vscale;          // wyb (zeroed if invalid)
            wyv[2 * t + 1] = ((float)yhI - py) * vscale;  // wyt (NOT 1-wyb)

            float px = x1b + ((float)t + 0.5f) * (bin_w * 0.5f);
            float xl = fminf(fmaxf(floorf(px), 0.f), (float)(FW - 1));
            int xlI = (int)xl;
            int xhI = min(xlI + 1, FW - 1);
            coli[2 * t + 0] = xlI * (CH / 2);
            coli[2 * t + 1] = xhI * (CH / 2);
            wxv[2 * t + 0] = px - xl;          // wxh
            wxv[2 * t + 1] = (float)xhI - px;  // wxl
        }
        // sameX <=> xl1==xl0 (then xh1==xh0 too); else xl1==xh0 (adjacency)
        int sameX = (coli[2] == coli[0]);
        int sameY = (rowi[2] == rowi[0]);
        g_rows[tid] = make_int4(rowi[0], rowi[1], rowi[3], sameX | (sameY << 1));
        g_cols[tid] = make_int4(coli[0], coli[1], coli[3], 0);
        g_wy[tid]   = make_float4(wyv[0], wyv[1], wyv[2], wyv[3]);
        g_wx[tid]   = make_float4(wxv[0], wxv[1], wxv[2], wxv[3]);
    }
    __syncthreads();

    // ---- Phase B ----
    int c2  = tid & 127;       // channel pair 0..127
    int grp = tid >> 7;        // bin group 0..3
    const float2* fb2 = fbase + c2;

    for (int k = grp; k < NBIN; k += NGRP) {
        int4   rw = g_rows[k];
        int4   cl = g_cols[k];
        float4 wy = g_wy[k];
        float4 wx = g_wx[k];
        bool sameX = rw.w & 1;
        bool sameY = rw.w & 2;

        // Base 2x2 corners (rows r0,r1 x cols c0,c1) — always needed.
        float2 f00 = fb2[rw.x + cl.x];
        float2 f01 = fb2[rw.x + cl.y];
        float2 f10 = fb2[rw.y + cl.x];
        float2 f11 = fb2[rw.y + cl.y];

        // x-interp for rows r0 (A) and r1 (B), both x-samples.
        float2 hA0 = xin(wx.x, wx.y, f01, f00);
        float2 hB0 = xin(wx.x, wx.y, f11, f10);
        float2 hA1, hB1;
        if (sameX) {
            hA1 = xin(wx.z, wx.w, f01, f00);
            hB1 = xin(wx.z, wx.w, f11, f10);
        } else {              // xl1 == xh0: new column c2 only
            float2 f02 = fb2[rw.x + cl.z];
            float2 f12 = fb2[rw.y + cl.z];
            hA1 = xin(wx.z, wx.w, f02, f01);
            hB1 = xin(wx.z, wx.w, f12, f11);
        }

        float m0 = -3.402823466e38f, m1 = -3.402823466e38f;
        // ty=0 samples: top row r0 (A), bottom row r1 (B)
        YMAX(m0, m1, wy.x, wy.y, hB0, hA0);
        YMAX(m0, m1, wy.x, wy.y, hB1, hA1);

        // ty=1 samples
        if (sameY) {          // rows identical: reuse hA/hB with wy1 weights
            YMAX(m0, m1, wy.z, wy.w, hB0, hA0);
            YMAX(m0, m1, wy.z, wy.w, hB1, hA1);
        } else {              // yl1 == yh0: top row r1 (B), bottom row r2 (C)
            float2 f20 = fb2[rw.z + cl.x];
            float2 f21 = fb2[rw.z + cl.y];
            float2 hC0 = xin(wx.x, wx.y, f21, f20);
            float2 hC1;
            if (sameX) {
                hC1 = xin(wx.z, wx.w, f21, f20);
            } else {
                float2 f22 = fb2[rw.z + cl.z];
                hC1 = xin(wx.z, wx.w, f22, f21);
            }
            YMAX(m0, m1, wy.z, wy.w, hC0, hB0);
            YMAX(m0, m1, wy.z, wy.w, hC1, hB1);
        }

        tile[(2 * c2 + 0) * NBIN + k] = m0;
        tile[(2 * c2 + 1) * NBIN + k] = m1;
    }
    __syncthreads();

    // ---- Phase C: tile[c*49 + k] is exactly (N,C,7,7) order for this roi ----
    float4* dst4       = (float4*)(out + (size_t)r * CH * NBIN);
    const float4* src4 = (const float4*)tile;
    for (int idx = tid; idx < CH * NBIN / 4; idx += blockDim.x)
        dst4[idx] = src4[idx];
}

extern "C" void kernel_launch(void* const* d_in, const int* in_sizes, int n_in,
                              void* d_out, int out_size) {
    const float* feats = (const float*)d_in[0];   // (4,256,50,50) f32
    const float* rois  = (const float*)d_in[1];   // (1024,5) f32
    float* out = (float*)d_out;                   // (1024,256,7,7) f32

    cudaFuncSetAttribute(roialign_kernel,
                         cudaFuncAttributeMaxDynamicSharedMemorySize, SMEM_BYTES);

    dim3 tgrid(CH / 32, (HW + 31) / 32, BATCH);
    dim3 tblk(32, 8);
    transpose_feats_kernel<<<tgrid, tblk>>>(feats);
    roialign_kernel<<<NROI, TPB, SMEM_BYTES>>>(rois, out);
}

// round 13
// speedup vs baseline: 1.2539x; 1.0192x over previous
#include <cuda_runtime.h>

#define FH 50
#define FW 50
#define CH 256
#define BATCH 4
#define NROI 1024
#define HOUT 7
#define WOUT 7
#define NBIN (HOUT*WOUT)
#define RATIO (1.0f/32.0f)
#define NGRP 4
#define TPB (128*NGRP)
#define HW (FH*FW)

// smem: tile[CH*NBIN] f32 + oA int4[NBIN] + fd int4[NBIN] + wy/wx float4[NBIN]
#define SMEM_BYTES (CH*NBIN*4 + NBIN*16*4)

// Features transposed to BHWC so channel reads are contiguous.
__device__ float g_feats[BATCH * HW * CH];

// ---------------------------------------------------------------------------
// Kernel 1: BCHW -> BHWC, classic 32x32 smem-tiled transpose per batch.
// ---------------------------------------------------------------------------
__global__ void transpose_feats_kernel(const float* __restrict__ in) {
    __shared__ float t[32][33];
    int b  = blockIdx.z;
    int c0 = blockIdx.x * 32;
    int p0 = blockIdx.y * 32;
    const float* src = in + (size_t)b * CH * HW;
    float* dst = g_feats + (size_t)b * HW * CH;

    int p = p0 + threadIdx.x;
#pragma unroll
    for (int i = 0; i < 32; i += 8) {
        int c = c0 + threadIdx.y + i;
        if (p < HW)
            t[threadIdx.y + i][threadIdx.x] = src[(size_t)c * HW + p];
    }
    __syncthreads();
    int c = c0 + threadIdx.x;
#pragma unroll
    for (int i = 0; i < 32; i += 8) {
        int pp = p0 + threadIdx.y + i;
        if (pp < HW)
            dst[(size_t)pp * CH + c] = t[threadIdx.x][threadIdx.y + i];
    }
}

// x-interp on a channel pair: xh*fh + xl*fl (reference expression form)
__device__ __forceinline__ float2 xin(float xh, float xl, float2 fh, float2 fl) {
    float2 r;
    r.x = xh * fh.x + xl * fl.x;
    r.y = xh * fh.y + xl * fl.y;
    return r;
}
// y-combine + max accumulate
#define YMAX(m0, m1, yb, yt, hb, ht)                   \
    do {                                               \
        m0 = fmaxf(m0, (yb) * (hb).x + (yt) * (ht).x); \
        m1 = fmaxf(m1, (yb) * (hb).y + (yt) * (ht).y); \
    } while (0)

// ---------------------------------------------------------------------------
// Kernel 2: RoIAlign. One block per FULL roi (grid 1024, 512 thr; regs ~40 ->
// 3 CTAs/SM, occ ~65%, verified R12). Factorized bilinear with adjacency
// reuse; base corner addresses PRE-SUMMED in Phase A (oA = row+col), extra
// corners addressed by single-add deltas (dcol/drow). First sample written
// directly into the max accumulators (no -inf init).
// ---------------------------------------------------------------------------
__global__ __launch_bounds__(TPB, 2)
void roialign_kernel(const float* __restrict__ rois,
                     float* __restrict__ out) {
    extern __shared__ float smem[];
    float*  tile  = smem;                               // [CH][NBIN]
    int4*   g_oA  = (int4*)(smem + CH * NBIN);          // [NBIN] r0c0,r0c1,r1c0,r1c1
    int4*   g_fd  = g_oA + NBIN;                        // [NBIN] dcol,drow,flags,0
    float4* g_wy  = (float4*)(g_fd + NBIN);             // [NBIN] wyb0,wyt0,wyb1,wyt1 (0 if invalid)
    float4* g_wx  = g_wy + NBIN;                        // [NBIN] wxh0,wxl0,wxh1,wxl1

    int r   = blockIdx.x;
    int tid = threadIdx.x;

    int b = (int)__ldg(&rois[r * 5 + 0]);
    const float2* fbase = (const float2*)g_feats + (size_t)b * HW * (CH / 2);

    // ---- Phase A ----
    if (tid < NBIN) {
        float bx1 = fminf(fmaxf(__ldg(&rois[r * 5 + 1]) * RATIO, 0.f), (float)FW);
        float by1 = fminf(fmaxf(__ldg(&rois[r * 5 + 2]) * RATIO, 0.f), (float)FH);
        float bx2 = fminf(fmaxf(__ldg(&rois[r * 5 + 3]) * RATIO, 0.f), (float)FW);
        float by2 = fminf(fmaxf(__ldg(&rois[r * 5 + 4]) * RATIO, 0.f), (float)FH);
        bool roi_valid = (bx2 - bx1 > 0.f) && (by2 - by1 > 0.f);
        float bin_w = (bx2 - bx1) * (1.0f / WOUT);
        float bin_h = (by2 - by1) * (1.0f / HOUT);

        int i = tid / WOUT;
        int j = tid - i * WOUT;

        float y1u = by1 + (float)i * bin_h;
        float y1b = fminf(fmaxf(y1u, 0.f), (float)FH);
        float y2b = fminf(fmaxf(y1u + bin_h, 0.f), (float)FH);
        float x1u = bx1 + (float)j * bin_w;
        float x1b = fminf(fmaxf(x1u, 0.f), (float)FW);
        float x2b = fminf(fmaxf(x1u + bin_w, 0.f), (float)FW);
        bool valid = roi_valid && (x2b > x1b) && (y2b > y1b);
        float vscale = valid ? 1.f : 0.f;

        int   rowi[4], coli[4];
        float wyv[4], wxv[4];
#pragma unroll
        for (int t = 0; t < 2; t++) {
            float py = y1b + ((float)t + 0.5f) * (bin_h * 0.5f);
            float yl = fminf(fmaxf(floorf(py), 0.f), (float)(FH - 1));
            int ylI = (int)yl;
            int yhI = min(ylI + 1, FH - 1);
            rowi[2 * t + 0] = ylI * FW * (CH / 2);
            rowi[2 * t + 1] = yhI * FW * (CH / 2);
            wyv[2 * t + 0] = (py - yl) * vscale;          // wyb (zeroed if invalid)
            wyv[2 * t + 1] = ((float)yhI - py) * vscale;  // wyt (NOT 1-wyb)

            float px = x1b + ((float)t + 0.5f) * (bin_w * 0.5f);
            float xl = fminf(fmaxf(floorf(px), 0.f), (float)(FW - 1));
            int xlI = (int)xl;
            int xhI = min(xlI + 1, FW - 1);
            coli[2 * t + 0] = xlI * (CH / 2);
            coli[2 * t + 1] = xhI * (CH / 2);
            wxv[2 * t + 0] = px - xl;          // wxh
            wxv[2 * t + 1] = (float)xhI - px;  // wxl
        }
        int sameX = (coli[2] == coli[0]);   // xl1==xl0 (else xl1==xh0 adjacency)
        int sameY = (rowi[2] == rowi[0]);
        // base 2x2 corners pre-summed (rows r0,r1 x cols c0,c1)
        g_oA[tid] = make_int4(rowi[0] + coli[0], rowi[0] + coli[1],
                              rowi[1] + coli[0], rowi[1] + coli[1]);
        // deltas to the new col (xh1 - xh0) / new row (yh1 - yh0); 0 at clamp
        // boundaries (then the "new" load aliases an existing one — correct).
        g_fd[tid] = make_int4(coli[3] - coli[1], rowi[3] - rowi[1],
                              sameX | (sameY << 1), 0);
        g_wy[tid] = make_float4(wyv[0], wyv[1], wyv[2], wyv[3]);
        g_wx[tid] = make_float4(wxv[0], wxv[1], wxv[2], wxv[3]);
    }
    __syncthreads();

    // ---- Phase B ----
    int c2  = tid & 127;       // channel pair 0..127
    int grp = tid >> 7;        // bin group 0..3
    const float2* fb2 = fbase + c2;
    float* trow0 = tile + (2 * c2 + 0) * NBIN;
    float* trow1 = tile + (2 * c2 + 1) * NBIN;

    for (int k = grp; k < NBIN; k += NGRP) {
        int4   oA = g_oA[k];
        int4   fd = g_fd[k];
        float4 wy = g_wy[k];
        float4 wx = g_wx[k];
        bool sameX = fd.z & 1;
        bool sameY = fd.z & 2;

        // Base 2x2 corners — always needed.
        float2 f00 = fb2[oA.x];
        float2 f01 = fb2[oA.y];
        float2 f10 = fb2[oA.z];
        float2 f11 = fb2[oA.w];

        // x-interp for rows r0 (A) and r1 (B), both x-samples.
        float2 hA0 = xin(wx.x, wx.y, f01, f00);
        float2 hB0 = xin(wx.x, wx.y, f11, f10);
        float2 hA1, hB1;
        if (sameX) {
            hA1 = xin(wx.z, wx.w, f01, f00);
            hB1 = xin(wx.z, wx.w, f11, f10);
        } else {              // xl1 == xh0: only column xh1 is new
            float2 f02 = fb2[oA.y + fd.x];
            float2 f12 = fb2[oA.w + fd.x];
            hA1 = xin(wx.z, wx.w, f02, f01);
            hB1 = xin(wx.z, wx.w, f12, f11);
        }

        // ty=0 samples: first one initializes the max directly.
        float m0 = wy.x * hB0.x + wy.y * hA0.x;
        float m1 = wy.x * hB0.y + wy.y * hA0.y;
        YMAX(m0, m1, wy.x, wy.y, hB1, hA1);

        // ty=1 samples
        if (sameY) {          // rows identical: reuse hA/hB with wy1 weights
            YMAX(m0, m1, wy.z, wy.w, hB0, hA0);
            YMAX(m0, m1, wy.z, wy.w, hB1, hA1);
        } else {              // yl1 == yh0: top row r1 (B), bottom row r2 (C)
            float2 f20 = fb2[oA.z + fd.y];
            float2 f21 = fb2[oA.w + fd.y];
            float2 hC0 = xin(wx.x, wx.y, f21, f20);
            float2 hC1;
            if (sameX) {
                hC1 = xin(wx.z, wx.w, f21, f20);
            } else {
                float2 f22 = fb2[oA.w + fd.y + fd.x];
                hC1 = xin(wx.z, wx.w, f22, f21);
            }
            YMAX(m0, m1, wy.z, wy.w, hC0, hB0);
            YMAX(m0, m1, wy.z, wy.w, hC1, hB1);
        }

        trow0[k] = m0;
        trow1[k] = m1;
    }
    __syncthreads();

    // ---- Phase C: tile[c*49 + k] is exactly (N,C,7,7) order for this roi ----
    float4* dst4       = (float4*)(out + (size_t)r * CH * NBIN);
    const float4* src4 = (const float4*)tile;
    for (int idx = tid; idx < CH * NBIN / 4; idx += blockDim.x)
        dst4[idx] = src4[idx];
}

extern "C" void kernel_launch(void* const* d_in, const int* in_sizes, int n_in,
                              void* d_out, int out_size) {
    const float* feats = (const float*)d_in[0];   // (4,256,50,50) f32
    const float* rois  = (const float*)d_in[1];   // (1024,5) f32
    float* out = (float*)d_out;                   // (1024,256,7,7) f32

    cudaFuncSetAttribute(roialign_kernel,
                         cudaFuncAttributeMaxDynamicSharedMemorySize, SMEM_BYTES);

    dim3 tgrid(CH / 32, (HW + 31) / 32, BATCH);
    dim3 tblk(32, 8);
    transpose_feats_kernel<<<tgrid, tblk>>>(feats);
    roialign_kernel<<<NROI, TPB, SMEM_BYTES>>>(rois, out);
}